// round 14
// baseline (speedup 1.0000x reference)
#include <cuda_runtime.h>
#include <cuda_bf16.h>
#include <cstdint>

#define NUM_C 46
#define WARPS 8
#define THREADS (WARPS * 32)
#define BLOCKS 888                         // 6 per SM on 148 SMs
#define NPART (3 * NUM_C)                  // 138: [col | tp | cnt]

// group = 2 chunks of 46 float4 = 92 float4 = 368 floats = 8 rows
#define GROUP_ROWS 8
#define GROUP_F4   92

__device__ float g_sum[NPART];             // zeroed at load; each launch restores it
__device__ unsigned int g_ticket = 0;

__global__ __launch_bounds__(THREADS, 6) void accum_kernel(
    const float* __restrict__ y_pred,
    const int* __restrict__ y_true,
    int n_rows,
    float* __restrict__ out)
{
    __shared__ float s_tp[NUM_C];
    __shared__ float s_cnt[NUM_C];
    __shared__ float s_col[NUM_C];
    __shared__ unsigned int s_rank;

    const int t    = threadIdx.x;
    const int wid  = t >> 5;
    const int lane = t & 31;

    if (t < NUM_C) {
        s_tp[t]  = 0.0f;
        s_cnt[t] = 0.0f;
        s_col[t] = 0.0f;
    }
    __syncthreads();

    const float4* src = reinterpret_cast<const float4*>(y_pred);
    const int ngroups     = n_rows / GROUP_ROWS;
    const int gwarp       = blockIdx.x * WARPS + wid;
    const int total_warps = gridDim.x * WARPS;

    // positional accumulators: lane owns float4 position `lane` (a0) and
    // `32+lane` (a1, lanes 0..13) inside every 46-float4 chunk.
    float a00 = 0.f, a01 = 0.f, a02 = 0.f, a03 = 0.f;
    float a10 = 0.f, a11 = 0.f, a12 = 0.f, a13 = 0.f;

    for (int gidx = gwarp; gidx < ngroups; gidx += total_warps) {
        const size_t base = (size_t)gidx * GROUP_F4;

        // positional loads (independent -> front-batched by ptxas)
        float4 x0 = src[base + lane];
        float4 x1 = src[base + 46 + lane];
        float4 y0, y1;
        if (lane < NUM_C - 32) {
            y0 = src[base + 32 + lane];
            y1 = src[base + 78 + lane];
        }

        // labels: 8 rows per group, lanes 0..7 (gather merges in L1 MSHR with
        // the positional loads covering the same sectors)
        const int row0 = gidx * GROUP_ROWS;
        if (lane < GROUP_ROWS) {
            const int lab = y_true[row0 + lane];
            const float v = y_pred[(size_t)(row0 + lane) * NUM_C + lab];
            atomicAdd(&s_tp[lab], v);
            atomicAdd(&s_cnt[lab], 1.0f);
        }

        a00 += x0.x + x1.x;  a01 += x0.y + x1.y;
        a02 += x0.z + x1.z;  a03 += x0.w + x1.w;
        if (lane < NUM_C - 32) {
            a10 += y0.x + y1.x;  a11 += y0.y + y1.y;
            a12 += y0.z + y1.z;  a13 += y0.w + y1.w;
        }
    }

    // scalar tail (n_rows not multiple of 8) — one warp handles it
    const int tail0 = ngroups * GROUP_ROWS;
    if (blockIdx.x == 0 && wid == 0) {
        for (int r = tail0; r < n_rows; r++) {
            const size_t off = (size_t)r * NUM_C;
            for (int i = lane; i < NUM_C; i += 32)
                atomicAdd(&s_col[i], y_pred[off + i]);
            if (lane == 0) {
                const int lab = y_true[r];
                atomicAdd(&s_tp[lab], y_pred[off + lab]);
                atomicAdd(&s_cnt[lab], 1.0f);
            }
        }
    }

    // flush positional accumulators to classes: pos p -> classes (4p+j)%46
    {
        const int p4 = 4 * lane;               // 4*p for a0 (p = lane)
        #pragma unroll
        for (int j = 0; j < 4; j++) {
            int c = p4 + j; if (c >= NUM_C) { c -= NUM_C; if (c >= NUM_C) c -= NUM_C; }
            atomicAdd(&s_col[c], (j == 0) ? a00 : (j == 1) ? a01 : (j == 2) ? a02 : a03);
        }
        if (lane < NUM_C - 32) {
            const int q4 = (4 * (32 + lane)) % NUM_C;   // = (128 + 4*lane) % 46
            #pragma unroll
            for (int j = 0; j < 4; j++) {
                int c = q4 + j; if (c >= NUM_C) c -= NUM_C;
                atomicAdd(&s_col[c], (j == 0) ? a10 : (j == 1) ? a11 : (j == 2) ? a12 : a13);
            }
        }
    }
    __syncthreads();

    // flush block partials straight to the global accumulators
    if (t < NPART) {
        float v = (t < NUM_C) ? s_col[t]
                : (t < 2 * NUM_C) ? s_tp[t - NUM_C]
                : s_cnt[t - 2 * NUM_C];
        atomicAdd(&g_sum[t], v);
    }
    __threadfence();
    __syncthreads();

    if (t == 0)
        s_rank = atomicAdd(&g_ticket, 1u);
    __syncthreads();

    if (s_rank == (unsigned)(gridDim.x - 1)) {
        // last block: all other blocks' atomics are globally visible
        __shared__ float s_f1[NUM_C];
        const float EPS = 1e-7f;
        volatile float* gs = g_sum;
        if (t < NUM_C) {
            float col_sum = gs[t];                // tp + fp
            float tp      = gs[NUM_C + t];
            float cnt     = gs[2 * NUM_C + t];    // tp + fn
            float precision = tp / (col_sum + EPS);
            float recall    = tp / (cnt + EPS);
            float f1 = 2.0f * precision * recall / (precision + recall + EPS);
            f1 = fminf(fmaxf(f1, EPS), 1.0f - EPS);
            s_f1[t] = f1;
        }
        __syncthreads();
        if (t == 0) {
            float sm = 0.0f;
            #pragma unroll
            for (int i = 0; i < NUM_C; i++) sm += s_f1[i];
            out[0] = 1.0f - sm / (float)NUM_C;
        }
        __syncthreads();
        // restore state for the next (graph-replayed) launch
        if (t < NPART) g_sum[t] = 0.0f;
        if (t == 0) g_ticket = 0u;
        __threadfence();
    }
}

extern "C" void kernel_launch(void* const* d_in, const int* in_sizes, int n_in,
                              void* d_out, int out_size) {
    const float* y_pred = (const float*)d_in[0];
    const int*   y_true = (const int*)d_in[1];
    float* out = (float*)d_out;

    const int n_rows = in_sizes[0] / NUM_C;   // derive from y_pred element count

    accum_kernel<<<BLOCKS, THREADS>>>(y_pred, y_true, n_rows, out);
}

// round 15
// speedup vs baseline: 1.0554x; 1.0554x over previous
#include <cuda_runtime.h>
#include <cuda_bf16.h>
#include <cstdint>

#define NUM_C 46
#define WARPS 8
#define THREADS (WARPS * 32)
#define WARP_ROWS 16
#define WTILE_FLOATS (WARP_ROWS * NUM_C)   // 736
#define WTILE_VEC (WTILE_FLOATS / 4)       // 184
#define BLOCKS 592                         // 4 per SM on 148 SMs (smem-limited)
#define NPART (3 * NUM_C)                  // 138: [col | tp | cnt]

__device__ float g_sum[NPART];             // zeroed at load; each launch restores it
__device__ unsigned int g_ticket = 0;

__device__ __forceinline__ void cp_async16(void* smem, const void* gmem) {
    uint32_t s = (uint32_t)__cvta_generic_to_shared(smem);
    asm volatile("cp.async.cg.shared.global [%0], [%1], 16;\n" :: "r"(s), "l"(gmem));
}
__device__ __forceinline__ void cp_async4(void* smem, const void* gmem) {
    uint32_t s = (uint32_t)__cvta_generic_to_shared(smem);
    asm volatile("cp.async.ca.shared.global [%0], [%1], 4;\n" :: "r"(s), "l"(gmem));
}
#define CP_COMMIT() asm volatile("cp.async.commit_group;\n" ::: "memory")
#define CP_WAIT(n)  asm volatile("cp.async.wait_group %0;\n" :: "n"(n) : "memory")

__global__ __launch_bounds__(THREADS) void accum_kernel(
    const float* __restrict__ y_pred,
    const int* __restrict__ y_true,
    int n_rows,
    float* __restrict__ out)
{
    __shared__ float s_buf[WARPS][2][WTILE_FLOATS];   // 47104 B
    __shared__ float s_tp[NUM_C];
    __shared__ float s_cnt[NUM_C];
    __shared__ float s_col[NUM_C];
    __shared__ unsigned int s_rank;

    const int t    = threadIdx.x;
    const int wid  = t >> 5;
    const int lane = t & 31;

    if (t < NUM_C) {
        s_tp[t]  = 0.0f;
        s_cnt[t] = 0.0f;
        s_col[t] = 0.0f;
    }

    const int num_wt  = (n_rows + WARP_ROWS - 1) / WARP_ROWS;
    const int wstride = gridDim.x * WARPS;

    // per-warp async copy of one 16-row tile into buffer b
    auto issue = [&](int wt_i, int b) {
        const int row0 = wt_i * WARP_ROWS;
        const int rows = min(WARP_ROWS, n_rows - row0);
        if (rows == WARP_ROWS) {
            const float4* src = reinterpret_cast<const float4*>(y_pred) +
                                (size_t)row0 * NUM_C / 4;
            float4* dst = reinterpret_cast<float4*>(s_buf[wid][b]);
            #pragma unroll
            for (int i = lane; i < WTILE_VEC; i += 32)
                cp_async16(&dst[i], &src[i]);
        } else {
            const int n_el = rows * NUM_C;
            const float* src = y_pred + (size_t)row0 * NUM_C;
            for (int i = lane; i < n_el; i += 32)
                cp_async4(&s_buf[wid][b][i], &src[i]);
        }
        CP_COMMIT();
    };

    int wt = blockIdx.x * WARPS + wid;
    if (wt < num_wt) issue(wt, 0);
    __syncthreads();       // one-time: covers s_tp/s_cnt/s_col zero-init

    float acc0 = 0.0f;     // class = lane        (0..31)
    float acc1 = 0.0f;     // class = 32 + lane   (lanes 0..13)

    int b = 0;
    for (; wt < num_wt; wt += wstride) {
        const int row0 = wt * WARP_ROWS;
        const int rows_here = min(WARP_ROWS, n_rows - row0);

        // hoist label load ABOVE the pipeline wait: its DRAM/L2 latency
        // overlaps the cp.async wait + column-sum chain instead of being
        // exposed before the shared atomics.
        int lab = 0;
        if (lane < rows_here)
            lab = y_true[row0 + lane];

        const int nxt = wt + wstride;
        if (nxt < num_wt) {
            issue(nxt, b ^ 1);
            CP_WAIT(1);          // current tile arrived; next may be in flight
        } else {
            CP_WAIT(0);
        }
        __syncwarp();            // all lanes' copies for this tile complete

        const float* tl = s_buf[wid][b];

        if (rows_here == WARP_ROWS) {
            #pragma unroll
            for (int r = 0; r < WARP_ROWS; r++) {
                acc0 += tl[r * NUM_C + lane];
                if (lane < NUM_C - 32)
                    acc1 += tl[r * NUM_C + 32 + lane];
            }
        } else {
            for (int r = 0; r < rows_here; r++) {
                acc0 += tl[r * NUM_C + lane];
                if (lane < NUM_C - 32)
                    acc1 += tl[r * NUM_C + 32 + lane];
            }
        }

        if (lane < rows_here) {
            atomicAdd(&s_tp[lab], tl[lane * NUM_C + lab]);
            atomicAdd(&s_cnt[lab], 1.0f);
        }
        __syncwarp();
        b ^= 1;
    }

    // flush per-lane class accumulators (8 warps contend lightly per class)
    atomicAdd(&s_col[lane], acc0);
    if (lane < NUM_C - 32)
        atomicAdd(&s_col[32 + lane], acc1);
    __syncthreads();

    // flush block partials straight to the global accumulators
    if (t < NPART) {
        float v = (t < NUM_C) ? s_col[t]
                : (t < 2 * NUM_C) ? s_tp[t - NUM_C]
                : s_cnt[t - 2 * NUM_C];
        atomicAdd(&g_sum[t], v);
    }
    __threadfence();
    __syncthreads();

    if (t == 0)
        s_rank = atomicAdd(&g_ticket, 1u);
    __syncthreads();

    if (s_rank == (unsigned)(gridDim.x - 1)) {
        // last block: all other blocks' atomics are globally visible
        __shared__ float s_f1[NUM_C];
        const float EPS = 1e-7f;
        volatile float* gs = g_sum;
        if (t < NUM_C) {
            float col_sum = gs[t];                // tp + fp
            float tp      = gs[NUM_C + t];
            float cnt     = gs[2 * NUM_C + t];    // tp + fn
            float precision = tp / (col_sum + EPS);
            float recall    = tp / (cnt + EPS);
            float f1 = 2.0f * precision * recall / (precision + recall + EPS);
            f1 = fminf(fmaxf(f1, EPS), 1.0f - EPS);
            s_f1[t] = f1;
        }
        __syncthreads();
        if (t == 0) {
            float sm = 0.0f;
            #pragma unroll
            for (int i = 0; i < NUM_C; i++) sm += s_f1[i];
            out[0] = 1.0f - sm / (float)NUM_C;
        }
        __syncthreads();
        // restore state for the next (graph-replayed) launch
        if (t < NPART) g_sum[t] = 0.0f;
        if (t == 0) g_ticket = 0u;
        __threadfence();
    }
}

extern "C" void kernel_launch(void* const* d_in, const int* in_sizes, int n_in,
                              void* d_out, int out_size) {
    const float* y_pred = (const float*)d_in[0];
    const int*   y_true = (const int*)d_in[1];
    float* out = (float*)d_out;

    const int n_rows = in_sizes[0] / NUM_C;   // derive from y_pred element count

    accum_kernel<<<BLOCKS, THREADS>>>(y_pred, y_true, n_rows, out);
}